// round 13
// baseline (speedup 1.0000x reference)
#include <cuda_runtime.h>
#include <cuda_fp16.h>
#include <mma.h>
#include <math.h>

using namespace nvcuda;

#define NN 100000
#define RR 3
#define EE 1600000
#define TOT (RR * NN)
#define SCAN_GRID 293
#define EB 1563            // blocks per relation for edge kernels (4 edges/thread)
#define ESTRIDE (EB * 256) // 400128 threads; 4*ESTRIDE >= EE

__device__ __align__(16) __half2 g_Z1h[RR][(long)NN * 64];
__device__ __align__(16) float g_EL1[RR][NN * 4];
__device__ __align__(16) float g_ER1[RR][NN * 4];
__device__ __align__(16) __half2 g_H1h[(long)NN * 64];
__device__ __align__(16) float g_Z2[RR][NN * 16];
__device__ __align__(16) float g_EL2[RR][NN];
__device__ __align__(16) float g_ER2[RR][NN];

__device__ int g_cnt[TOT];
__device__ int g_off[TOT];
__device__ int g_cur[TOT];
__device__ int g_grand;
__device__ int g_csrc[RR * EE];

struct __align__(8) h4 { __half2 a, b; };

__device__ __forceinline__ float lrexp(float a, float b) {
    float e = a + b;
    e = e > 0.f ? e : 0.2f * e;
    return __expf(e);
}

// ---------------- CSR build ----------------
__global__ void k_zero_cnt() {
    int i = blockIdx.x * 256 + threadIdx.x;
    if (i < TOT) g_cnt[i] = 0;
    if (i == 0) g_grand = 0;
}

// 4 edges per thread, WARP-STRIDE batched: coalesced loads + 4 atomic chains
__global__ __launch_bounds__(256) void k_hist(const int* __restrict__ dst) {
    int rel = blockIdx.y;
    int t = blockIdx.x * 256 + threadIdx.x;
    const int* dp = dst + (long)rel * EE;
    int cb = rel * NN;
#pragma unroll
    for (int k = 0; k < 4; k++) {
        int e = t + k * ESTRIDE;
        if (e < EE) atomicAdd(&g_cnt[cb + dp[e]], 1);
    }
}

// fused scan: block-local exclusive scan + atomic block base (offsets disjoint)
__global__ __launch_bounds__(256) void k_scanF() {
    __shared__ int ssum[256];
    __shared__ int sbase;
    int t = threadIdx.x;
    int base = blockIdx.x * 1024 + t * 4;
    int v0 = (base + 0 < TOT) ? g_cnt[base + 0] : 0;
    int v1 = (base + 1 < TOT) ? g_cnt[base + 1] : 0;
    int v2 = (base + 2 < TOT) ? g_cnt[base + 2] : 0;
    int v3 = (base + 3 < TOT) ? g_cnt[base + 3] : 0;
    int tsum = v0 + v1 + v2 + v3;
    ssum[t] = tsum;
    __syncthreads();
    for (int off = 1; off < 256; off <<= 1) {
        int xv = (t >= off) ? ssum[t - off] : 0;
        __syncthreads();
        ssum[t] += xv;
        __syncthreads();
    }
    if (t == 255) sbase = atomicAdd(&g_grand, ssum[255]);
    __syncthreads();
    int run = ssum[t] - tsum + sbase;
    if (base + 0 < TOT) { g_off[base + 0] = run; g_cur[base + 0] = run; }
    run += v0;
    if (base + 1 < TOT) { g_off[base + 1] = run; g_cur[base + 1] = run; }
    run += v1;
    if (base + 2 < TOT) { g_off[base + 2] = run; g_cur[base + 2] = run; }
    run += v2;
    if (base + 3 < TOT) { g_off[base + 3] = run; g_cur[base + 3] = run; }
}

// 4 edges per thread, warp-stride batched
__global__ __launch_bounds__(256) void k_scatter(const int* __restrict__ src,
                                                 const int* __restrict__ dst) {
    int rel = blockIdx.y;
    int t = blockIdx.x * 256 + threadIdx.x;
    const int* sp = src + (long)rel * EE;
    const int* dp = dst + (long)rel * EE;
    int cb = rel * NN;
    int s[4];
    int d[4];
#pragma unroll
    for (int k = 0; k < 4; k++) {
        int e = t + k * ESTRIDE;
        if (e < EE) { s[k] = sp[e]; d[k] = dp[e]; } else { d[k] = -1; }
    }
    int pos[4];
#pragma unroll
    for (int k = 0; k < 4; k++) {
        if (d[k] >= 0) pos[k] = atomicAdd(&g_cur[cb + d[k]], 1);
    }
#pragma unroll
    for (int k = 0; k < 4; k++) {
        if (d[k] >= 0) g_csrc[pos[k]] = s[k];
    }
}

// ------- layer1 GEMM, 3 relations fused per CTA, dynamic smem ---------------
#define FSTR 136
__global__ __launch_bounds__(256) void k_gemm1f(const float* __restrict__ x,
                                                const float* __restrict__ W1,
                                                const float* __restrict__ al1,
                                                const float* __restrict__ ar1) {
    extern __shared__ __align__(16) char dsm[];
    __half* As = (__half*)dsm;                  // 128*136 halves = 34816 B
    __half* Bs = (__half*)(dsm + 34816);        // 34816 B (also St)
    float* scratch = (float*)(dsm + 69632);     // 8 warps * 256 f = 8192 B
    __shared__ float alS[384];
    __shared__ float arS[384];
    int row0 = blockIdx.x * 128;
    int tid = threadIdx.x;
    int lane = tid & 31;
    int warp = tid >> 5;
    int mw = warp & 3;
    int nw = warp >> 2;

    if (tid < 128) {
#pragma unroll
        for (int r = 0; r < RR; r++) {
            alS[r * 128 + tid] = al1[r * 128 + tid];
            arS[r * 128 + tid] = ar1[r * 128 + tid];
        }
    }

#pragma unroll
    for (int i = 0; i < 16; i++) {
        int lin = tid + i * 256;
        int r = lin >> 5;
        int c4 = lin & 31;
        int gr = row0 + r;
        if (gr >= NN) gr = NN - 1;
        float4 v = *(const float4*)(x + (long)gr * 128 + c4 * 4);
        __half2* p = (__half2*)(As + r * FSTR + c4 * 4);
        p[0] = __floats2half2_rn(v.x, v.y);
        p[1] = __floats2half2_rn(v.z, v.w);
    }

    for (int rel = 0; rel < RR; rel++) {
        const float* Wp = W1 + (long)rel * 16384;
#pragma unroll
        for (int i = 0; i < 16; i++) {
            int lin = tid + i * 256;
            int r = lin >> 5;
            int c4 = lin & 31;
            float4 v = *(const float4*)(Wp + (long)r * 128 + c4 * 4);
            __half2* p = (__half2*)(Bs + r * FSTR + c4 * 4);
            p[0] = __floats2half2_rn(v.x, v.y);
            p[1] = __floats2half2_rn(v.z, v.w);
        }
        __syncthreads();

        wmma::fragment<wmma::accumulator, 16, 16, 16, float> acc0[4];
        wmma::fragment<wmma::accumulator, 16, 16, 16, float> acc1[4];
#pragma unroll
        for (int nt = 0; nt < 4; nt++) {
            wmma::fill_fragment(acc0[nt], 0.f);
            wmma::fill_fragment(acc1[nt], 0.f);
        }
#pragma unroll
        for (int ks = 0; ks < 8; ks++) {
            int k0 = ks * 16;
            wmma::fragment<wmma::matrix_a, 16, 16, 16, __half, wmma::row_major> af0;
            wmma::fragment<wmma::matrix_a, 16, 16, 16, __half, wmma::row_major> af1;
            wmma::load_matrix_sync(af0, As + (mw * 32) * FSTR + k0, FSTR);
            wmma::load_matrix_sync(af1, As + (mw * 32 + 16) * FSTR + k0, FSTR);
#pragma unroll
            for (int nt = 0; nt < 4; nt++) {
                wmma::fragment<wmma::matrix_b, 16, 16, 16, __half, wmma::row_major> bf;
                wmma::load_matrix_sync(bf, Bs + k0 * FSTR + nw * 64 + nt * 16, FSTR);
                wmma::mma_sync(acc0[nt], af0, bf, acc0[nt]);
                wmma::mma_sync(acc1[nt], af1, bf, acc1[nt]);
            }
        }
        __syncthreads();   // done reading Bs; reuse as staging tile

        __half* St = Bs;
        float* myscr = scratch + warp * 256;
#pragma unroll
        for (int mt = 0; mt < 2; mt++) {
#pragma unroll
            for (int nt = 0; nt < 4; nt++) {
                if (mt == 0) {
                    wmma::store_matrix_sync(myscr, acc0[nt], 16, wmma::mem_row_major);
                } else {
                    wmma::store_matrix_sync(myscr, acc1[nt], 16, wmma::mem_row_major);
                }
                __syncwarp();
#pragma unroll
                for (int q = 0; q < 4; q++) {
                    int idx = lane + q * 32;
                    int rr = idx >> 3;
                    int cc = (idx & 7) * 2;
                    __half2 hv = __floats2half2_rn(myscr[rr * 16 + cc],
                                                   myscr[rr * 16 + cc + 1]);
                    int gr2 = mw * 32 + mt * 16 + rr;
                    int gc = nw * 64 + nt * 16 + cc;
                    *(__half2*)(St + gr2 * FSTR + gc) = hv;
                }
                __syncwarp();
            }
        }
        __syncthreads();

#pragma unroll
        for (int i = 0; i < 8; i++) {
            int lin = tid + i * 256;
            int r = lin >> 4;
            int ch = lin & 15;
            int gr = row0 + r;
            if (gr < NN) {
                float4 v = *(const float4*)(St + r * FSTR + ch * 8);
                *(float4*)(&g_Z1h[rel][(long)gr * 64 + ch * 4]) = v;
            }
        }
#pragma unroll
        for (int pp = 0; pp < 2; pp++) {
            int idx = tid + pp * 256;
            int r = idx >> 2;
            int h = idx & 3;
            int gr = row0 + r;
            if (gr < NN) {
                const __half2* zp = (const __half2*)(St + r * FSTR + h * 32);
                const float* alp = alS + rel * 128 + h * 32;
                const float* arp = arS + rel * 128 + h * 32;
                float el = 0.f;
                float er = 0.f;
#pragma unroll
                for (int f = 0; f < 16; f++) {
                    float2 z2 = __half22float2(zp[f]);
                    el += z2.x * alp[2 * f] + z2.y * alp[2 * f + 1];
                    er += z2.x * arp[2 * f] + z2.y * arp[2 * f + 1];
                }
                g_EL1[rel][gr * 4 + h] = el;
                g_ER1[rel][gr * 4 + h] = er;
            }
        }
        __syncthreads();
    }
}

// ------- layer1 fused CSR aggregation: hoisted metadata, 8-way, fp16 out -----
__global__ __launch_bounds__(256) void k_agg1csr(const float* __restrict__ b1) {
    int w = (blockIdx.x * 256 + threadIdx.x) >> 5;
    if (w >= NN) return;
    int d = w;
    int lane = threadIdx.x & 31, h = lane >> 3;
    float acc0 = 0.f, acc1 = 0.f, acc2 = 0.f, acc3 = 0.f;

    int baseA[RR];
    int cntA[RR];
    float erv[RR];
#pragma unroll
    for (int rel = 0; rel < RR; rel++) {
        int idx = rel * NN + d;
        baseA[rel] = g_off[idx];
        cntA[rel] = g_cnt[idx];
        erv[rel] = g_ER1[rel][d * 4 + h];
    }

#pragma unroll
    for (int rel = 0; rel < RR; rel++) {
        float er = erv[rel];
        int base = baseA[rel], n = cntA[rel];
        float a0 = 0.f, a1 = 0.f, a2 = 0.f, a3 = 0.f, den = 0.f;
        int i = 0;
        for (; i + 8 <= n; i += 8) {
            int s0 = g_csrc[base + i];
            int s1 = g_csrc[base + i + 1];
            int s2 = g_csrc[base + i + 2];
            int s3 = g_csrc[base + i + 3];
            int s4 = g_csrc[base + i + 4];
            int s5 = g_csrc[base + i + 5];
            int s6 = g_csrc[base + i + 6];
            int s7 = g_csrc[base + i + 7];
            float el0 = g_EL1[rel][s0 * 4 + h];
            float el1 = g_EL1[rel][s1 * 4 + h];
            float el2 = g_EL1[rel][s2 * 4 + h];
            float el3 = g_EL1[rel][s3 * 4 + h];
            float el4 = g_EL1[rel][s4 * 4 + h];
            float el5 = g_EL1[rel][s5 * 4 + h];
            float el6 = g_EL1[rel][s6 * 4 + h];
            float el7 = g_EL1[rel][s7 * 4 + h];
            h4 z0 = *(const h4*)&g_Z1h[rel][(long)s0 * 64 + lane * 2];
            h4 z1 = *(const h4*)&g_Z1h[rel][(long)s1 * 64 + lane * 2];
            h4 z2 = *(const h4*)&g_Z1h[rel][(long)s2 * 64 + lane * 2];
            h4 z3 = *(const h4*)&g_Z1h[rel][(long)s3 * 64 + lane * 2];
            h4 z4 = *(const h4*)&g_Z1h[rel][(long)s4 * 64 + lane * 2];
            h4 z5 = *(const h4*)&g_Z1h[rel][(long)s5 * 64 + lane * 2];
            h4 z6 = *(const h4*)&g_Z1h[rel][(long)s6 * 64 + lane * 2];
            h4 z7 = *(const h4*)&g_Z1h[rel][(long)s7 * 64 + lane * 2];
            float p0 = lrexp(el0, er);
            float p1 = lrexp(el1, er);
            float p2 = lrexp(el2, er);
            float p3 = lrexp(el3, er);
            float p4 = lrexp(el4, er);
            float p5 = lrexp(el5, er);
            float p6 = lrexp(el6, er);
            float p7 = lrexp(el7, er);
            float2 q0 = __half22float2(z0.a), r0 = __half22float2(z0.b);
            float2 q1 = __half22float2(z1.a), r1 = __half22float2(z1.b);
            float2 q2 = __half22float2(z2.a), r2 = __half22float2(z2.b);
            float2 q3 = __half22float2(z3.a), r3 = __half22float2(z3.b);
            float2 q4 = __half22float2(z4.a), r4 = __half22float2(z4.b);
            float2 q5 = __half22float2(z5.a), r5 = __half22float2(z5.b);
            float2 q6 = __half22float2(z6.a), r6 = __half22float2(z6.b);
            float2 q7 = __half22float2(z7.a), r7 = __half22float2(z7.b);
            a0 += p0 * q0.x + p1 * q1.x + p2 * q2.x + p3 * q3.x
                + p4 * q4.x + p5 * q5.x + p6 * q6.x + p7 * q7.x;
            a1 += p0 * q0.y + p1 * q1.y + p2 * q2.y + p3 * q3.y
                + p4 * q4.y + p5 * q5.y + p6 * q6.y + p7 * q7.y;
            a2 += p0 * r0.x + p1 * r1.x + p2 * r2.x + p3 * r3.x
                + p4 * r4.x + p5 * r5.x + p6 * r6.x + p7 * r7.x;
            a3 += p0 * r0.y + p1 * r1.y + p2 * r2.y + p3 * r3.y
                + p4 * r4.y + p5 * r5.y + p6 * r6.y + p7 * r7.y;
            den += p0 + p1 + p2 + p3 + p4 + p5 + p6 + p7;
        }
        for (; i < n; i++) {
            int s = g_csrc[base + i];
            float p = lrexp(g_EL1[rel][s * 4 + h], er);
            h4 z = *(const h4*)&g_Z1h[rel][(long)s * 64 + lane * 2];
            float2 zlo = __half22float2(z.a), zhi = __half22float2(z.b);
            a0 += p * zlo.x; a1 += p * zlo.y; a2 += p * zhi.x; a3 += p * zhi.y;
            den += p;
        }
        float rden = (n > 0) ? __frcp_rn(den) : 0.f;
        acc0 += a0 * rden; acc1 += a1 * rden; acc2 += a2 * rden; acc3 += a3 * rden;
    }
    int c = lane * 4;
    float4 bA = *(const float4*)(b1 + c);
    float4 bB = *(const float4*)(b1 + 128 + c);
    float4 bC = *(const float4*)(b1 + 256 + c);
    float v0 = (acc0 + bA.x + bB.x + bC.x) * (1.f / 3.f);
    float v1 = (acc1 + bA.y + bB.y + bC.y) * (1.f / 3.f);
    float v2 = (acc2 + bA.z + bB.z + bC.z) * (1.f / 3.f);
    float v3 = (acc3 + bA.w + bB.w + bC.w) * (1.f / 3.f);
    v0 = v0 > 0.f ? v0 : expm1f(v0);
    v1 = v1 > 0.f ? v1 : expm1f(v1);
    v2 = v2 > 0.f ? v2 : expm1f(v2);
    v3 = v3 > 0.f ? v3 : expm1f(v3);
    h4 hv;
    hv.a = __floats2half2_rn(v0, v1);
    hv.b = __floats2half2_rn(v2, v3);
    *(h4*)(&g_H1h[(long)d * 64 + lane * 2]) = hv;
}

// ---------------- layer2 GEMM via wmma (fp16 H1h input) ----------------------
#define A2STR 136
#define B2STR 24
__global__ __launch_bounds__(256) void k_gemm2_wmma(const float* __restrict__ W2,
                                                    const float* __restrict__ al2,
                                                    const float* __restrict__ ar2) {
    __shared__ __align__(16) char smraw2[40960];
    __shared__ float al2S[16];
    __shared__ float ar2S[16];
    __half* As2 = (__half*)smraw2;
    __half* Bs2 = (__half*)(smraw2 + 34816);
    int rel = blockIdx.z;
    int row0 = blockIdx.x * 128;
    int tid = threadIdx.x;
    int lane = tid & 31;
    int warp = tid >> 5;

    if (tid < 16) {
        al2S[tid] = al2[rel * 16 + tid];
        ar2S[tid] = ar2[rel * 16 + tid];
    }

#pragma unroll
    for (int i = 0; i < 8; i++) {
        int lin = tid + i * 256;
        int r = lin >> 4;
        int ch = lin & 15;
        int gr = row0 + r;
        if (gr >= NN) gr = NN - 1;
        float4 v = *(const float4*)(&g_H1h[(long)gr * 64 + ch * 4]);
        *(float4*)(As2 + r * A2STR + ch * 8) = v;
    }
#pragma unroll
    for (int i = 0; i < 8; i++) {
        int idx = tid + i * 256;
        int r = idx >> 4;
        int c = idx & 15;
        float v = W2[(long)rel * 2048 + r * 16 + c];
        Bs2[r * B2STR + c] = __float2half_rn(v);
    }
    __syncthreads();

    wmma::fragment<wmma::accumulator, 16, 16, 16, float> acc;
    wmma::fill_fragment(acc, 0.f);
#pragma unroll
    for (int ks = 0; ks < 8; ks++) {
        int k0 = ks * 16;
        wmma::fragment<wmma::matrix_a, 16, 16, 16, __half, wmma::row_major> af;
        wmma::fragment<wmma::matrix_b, 16, 16, 16, __half, wmma::row_major> bf;
        wmma::load_matrix_sync(af, As2 + (warp * 16) * A2STR + k0, A2STR);
        wmma::load_matrix_sync(bf, Bs2 + k0 * B2STR, B2STR);
        wmma::mma_sync(acc, af, bf, acc);
    }
    __syncthreads();

    float* scr = (float*)smraw2 + warp * 256;
    wmma::store_matrix_sync(scr, acc, 16, wmma::mem_row_major);
    __syncwarp();

#pragma unroll
    for (int q = 0; q < 8; q++) {
        int idx = lane + q * 32;
        int rr = idx >> 4;
        int cc = idx & 15;
        int row = row0 + warp * 16 + rr;
        if (row < NN) g_Z2[rel][(long)row * 16 + cc] = scr[rr * 16 + cc];
    }
    if (lane < 16) {
        int row = row0 + warp * 16 + lane;
        if (row < NN) {
            float el = 0.f;
            float er = 0.f;
#pragma unroll
            for (int j = 0; j < 16; j++) {
                float zv = scr[lane * 16 + j];
                el += zv * al2S[j];
                er += zv * ar2S[j];
            }
            g_EL2[rel][row] = el;
            g_ER2[rel][row] = er;
        }
    }
}

// ---------------- layer2 fused CSR aggregation (4 per half-warp) -------------
__global__ __launch_bounds__(256) void k_agg2csr(const float* __restrict__ b2,
                                                 float* __restrict__ out) {
    int w = (blockIdx.x * 256 + threadIdx.x) >> 5;
    if (w >= NN) return;
    int d = w;
    int lane = threadIdx.x & 31, hh = lane >> 4, c = lane & 15;
    float acc = 0.f;

#pragma unroll
    for (int rel = 0; rel < RR; rel++) {
        float er = g_ER2[rel][d];
        int idx = rel * NN + d;
        int base = g_off[idx], n = g_cnt[idx];
        float aR = 0.f, den = 0.f;
        int i = hh;
        for (; i + 6 < n; i += 8) {
            int s0 = g_csrc[base + i];
            int s1 = g_csrc[base + i + 2];
            int s2 = g_csrc[base + i + 4];
            int s3 = g_csrc[base + i + 6];
            float e0 = g_EL2[rel][s0];
            float e1 = g_EL2[rel][s1];
            float e2 = g_EL2[rel][s2];
            float e3 = g_EL2[rel][s3];
            float za = g_Z2[rel][s0 * 16 + c];
            float zb = g_Z2[rel][s1 * 16 + c];
            float zc = g_Z2[rel][s2 * 16 + c];
            float zd = g_Z2[rel][s3 * 16 + c];
            float p0 = lrexp(e0, er);
            float p1 = lrexp(e1, er);
            float p2 = lrexp(e2, er);
            float p3 = lrexp(e3, er);
            aR += p0 * za + p1 * zb + p2 * zc + p3 * zd;
            den += p0 + p1 + p2 + p3;
        }
        for (; i < n; i += 2) {
            int s = g_csrc[base + i];
            float p = lrexp(g_EL2[rel][s], er);
            aR += p * g_Z2[rel][s * 16 + c];
            den += p;
        }
        den += __shfl_xor_sync(0xffffffffu, den, 16);
        float rden = (n > 0) ? __frcp_rn(den) : 0.f;
        acc += aR * rden;
    }
    acc += __shfl_xor_sync(0xffffffffu, acc, 16);
    if (hh == 0) {
        float bs = b2[c] + b2[16 + c] + b2[32 + c];
        out[d * 16 + c] = (acc + bs) * (1.f / 3.f);
    }
}

// ---------------- launcher ----------------
extern "C" void kernel_launch(void* const* d_in, const int* in_sizes, int n_in,
                              void* d_out, int out_size) {
    const float* x   = (const float*)d_in[0];
    const int*   src = (const int*)d_in[1];
    const int*   dst = (const int*)d_in[2];
    const float* W1  = (const float*)d_in[3];
    const float* al1 = (const float*)d_in[4];
    const float* ar1 = (const float*)d_in[5];
    const float* b1  = (const float*)d_in[6];
    const float* W2  = (const float*)d_in[7];
    const float* al2 = (const float*)d_in[8];
    const float* ar2 = (const float*)d_in[9];
    const float* b2  = (const float*)d_in[10];
    float* out = (float*)d_out;

    cudaFuncSetAttribute(k_gemm1f, cudaFuncAttributeMaxDynamicSharedMemorySize,
                         77824);

    k_zero_cnt<<<(TOT + 255) / 256, 256>>>();
    dim3 geb(EB, RR);
    k_hist<<<geb, 256>>>(dst);
    k_scanF<<<SCAN_GRID, 256>>>();

    k_gemm1f<<<(NN + 127) / 128, 256, 77824>>>(x, W1, al1, ar1);  // idx 3 (profiled)

    k_scatter<<<geb, 256>>>(src, dst);

    k_agg1csr<<<(NN * 32 + 255) / 256, 256>>>(b1);

    dim3 gm((NN + 127) / 128, 1, RR);
    k_gemm2_wmma<<<gm, 256>>>(W2, al2, ar2);
    k_agg2csr<<<(NN * 32 + 255) / 256, 256>>>(b2, out);
}

// round 14
// speedup vs baseline: 1.0814x; 1.0814x over previous
#include <cuda_runtime.h>
#include <cuda_fp16.h>
#include <mma.h>
#include <math.h>

using namespace nvcuda;

#define NN 100000
#define RR 3
#define EE 1600000
#define TOT (RR * NN)
#define SCAN_GRID 293

__device__ __align__(16) __half2 g_Z1h[RR][(long)NN * 64];
__device__ __align__(16) float g_EL1[RR][NN * 4];
__device__ __align__(16) float g_ER1[RR][NN * 4];
__device__ __align__(16) __half2 g_H1h[(long)NN * 64];
__device__ __align__(16) float g_Z2[RR][NN * 16];
__device__ __align__(16) float g_EL2[RR][NN];
__device__ __align__(16) float g_ER2[RR][NN];

__device__ int g_cnt[TOT];
__device__ int g_off[TOT];
__device__ int g_cur[TOT];
__device__ int g_grand;
__device__ int g_csrc[RR * EE];

struct __align__(8) h4 { __half2 a, b; };
struct __align__(16) h8 { __half2 a, b, c, d; };

__device__ __forceinline__ float lrexp(float a, float b) {
    float e = a + b;
    e = e > 0.f ? e : 0.2f * e;
    return __expf(e);
}

// ---------------- CSR build (R11-proven one-edge-per-thread form) ------------
__global__ void k_zero_cnt() {
    int i = blockIdx.x * 256 + threadIdx.x;
    if (i < TOT) g_cnt[i] = 0;
    if (i == 0) g_grand = 0;
}

__global__ __launch_bounds__(256) void k_hist(const int* __restrict__ dst) {
    int rel = blockIdx.y;
    long e = blockIdx.x * 256L + threadIdx.x;
    if (e >= EE) return;
    int d = dst[(long)rel * EE + e];
    atomicAdd(&g_cnt[rel * NN + d], 1);
}

__global__ __launch_bounds__(256) void k_scanF() {
    __shared__ int ssum[256];
    __shared__ int sbase;
    int t = threadIdx.x;
    int base = blockIdx.x * 1024 + t * 4;
    int v0 = (base + 0 < TOT) ? g_cnt[base + 0] : 0;
    int v1 = (base + 1 < TOT) ? g_cnt[base + 1] : 0;
    int v2 = (base + 2 < TOT) ? g_cnt[base + 2] : 0;
    int v3 = (base + 3 < TOT) ? g_cnt[base + 3] : 0;
    int tsum = v0 + v1 + v2 + v3;
    ssum[t] = tsum;
    __syncthreads();
    for (int off = 1; off < 256; off <<= 1) {
        int xv = (t >= off) ? ssum[t - off] : 0;
        __syncthreads();
        ssum[t] += xv;
        __syncthreads();
    }
    if (t == 255) sbase = atomicAdd(&g_grand, ssum[255]);
    __syncthreads();
    int run = ssum[t] - tsum + sbase;
    if (base + 0 < TOT) { g_off[base + 0] = run; g_cur[base + 0] = run; }
    run += v0;
    if (base + 1 < TOT) { g_off[base + 1] = run; g_cur[base + 1] = run; }
    run += v1;
    if (base + 2 < TOT) { g_off[base + 2] = run; g_cur[base + 2] = run; }
    run += v2;
    if (base + 3 < TOT) { g_off[base + 3] = run; g_cur[base + 3] = run; }
}

__global__ __launch_bounds__(256) void k_scatter(const int* __restrict__ src,
                                                 const int* __restrict__ dst) {
    int rel = blockIdx.y;
    long e = blockIdx.x * 256L + threadIdx.x;
    if (e >= EE) return;
    int s = src[(long)rel * EE + e];
    int d = dst[(long)rel * EE + e];
    int pos = atomicAdd(&g_cur[rel * NN + d], 1);
    g_csrc[pos] = s;
}

// ------- layer1 GEMM, 3 rels fused, direct-from-scratch epilogue -------------
#define FSTR 136
__global__ __launch_bounds__(256) void k_gemm1f(const float* __restrict__ x,
                                                const float* __restrict__ W1,
                                                const float* __restrict__ al1,
                                                const float* __restrict__ ar1) {
    extern __shared__ __align__(16) char dsm[];
    __half* As = (__half*)dsm;                  // 128*136 halves = 34816 B
    __half* Bs = (__half*)(dsm + 34816);        // 34816 B
    float* scratch = (float*)(dsm + 69632);     // 8 warps * 256 f = 8192 B
    __shared__ float alS[384];
    __shared__ float arS[384];
    int row0 = blockIdx.x * 128;
    int tid = threadIdx.x;
    int lane = tid & 31;
    int warp = tid >> 5;
    int mw = warp & 3;
    int nw = warp >> 2;

    if (tid < 128) {
#pragma unroll
        for (int r = 0; r < RR; r++) {
            alS[r * 128 + tid] = al1[r * 128 + tid];
            arS[r * 128 + tid] = ar1[r * 128 + tid];
        }
    }

    // A fill once: 128 rows x 128 cols fp32 -> fp16
#pragma unroll
    for (int i = 0; i < 16; i++) {
        int lin = tid + i * 256;
        int r = lin >> 5;
        int c4 = lin & 31;
        int gr = row0 + r;
        if (gr >= NN) gr = NN - 1;
        float4 v = *(const float4*)(x + (long)gr * 128 + c4 * 4);
        __half2* p = (__half2*)(As + r * FSTR + c4 * 4);
        p[0] = __floats2half2_rn(v.x, v.y);
        p[1] = __floats2half2_rn(v.z, v.w);
    }

    float* myscr = scratch + warp * 256;
    int rr = lane >> 1;          // scratch tile row (0..15)
    int ch = lane & 1;           // col half (8 floats each)

    for (int rel = 0; rel < RR; rel++) {
        const float* Wp = W1 + (long)rel * 16384;
#pragma unroll
        for (int i = 0; i < 16; i++) {
            int lin = tid + i * 256;
            int r = lin >> 5;
            int c4 = lin & 31;
            float4 v = *(const float4*)(Wp + (long)r * 128 + c4 * 4);
            __half2* p = (__half2*)(Bs + r * FSTR + c4 * 4);
            p[0] = __floats2half2_rn(v.x, v.y);
            p[1] = __floats2half2_rn(v.z, v.w);
        }
        __syncthreads();

        wmma::fragment<wmma::accumulator, 16, 16, 16, float> acc0[4];
        wmma::fragment<wmma::accumulator, 16, 16, 16, float> acc1[4];
#pragma unroll
        for (int nt = 0; nt < 4; nt++) {
            wmma::fill_fragment(acc0[nt], 0.f);
            wmma::fill_fragment(acc1[nt], 0.f);
        }
#pragma unroll
        for (int ks = 0; ks < 8; ks++) {
            int k0 = ks * 16;
            wmma::fragment<wmma::matrix_a, 16, 16, 16, __half, wmma::row_major> af0;
            wmma::fragment<wmma::matrix_a, 16, 16, 16, __half, wmma::row_major> af1;
            wmma::load_matrix_sync(af0, As + (mw * 32) * FSTR + k0, FSTR);
            wmma::load_matrix_sync(af1, As + (mw * 32 + 16) * FSTR + k0, FSTR);
#pragma unroll
            for (int nt = 0; nt < 4; nt++) {
                wmma::fragment<wmma::matrix_b, 16, 16, 16, __half, wmma::row_major> bf;
                wmma::load_matrix_sync(bf, Bs + k0 * FSTR + nw * 64 + nt * 16, FSTR);
                wmma::mma_sync(acc0[nt], af0, bf, acc0[nt]);
                wmma::mma_sync(acc1[nt], af1, bf, acc1[nt]);
            }
        }

        // direct epilogue: per warp, per mt; z + el/er straight from scratch
#pragma unroll
        for (int mt = 0; mt < 2; mt++) {
            int gr2 = row0 + mw * 32 + mt * 16 + rr;
            bool ok = gr2 < NN;
            float peA = 0.f, prA = 0.f, peB = 0.f, prB = 0.f;
#pragma unroll
            for (int nt = 0; nt < 4; nt++) {
                if (mt == 0) {
                    wmma::store_matrix_sync(myscr, acc0[nt], 16, wmma::mem_row_major);
                } else {
                    wmma::store_matrix_sync(myscr, acc1[nt], 16, wmma::mem_row_major);
                }
                __syncwarp();
                float v0 = myscr[rr * 16 + ch * 8 + 0];
                float v1 = myscr[rr * 16 + ch * 8 + 1];
                float v2 = myscr[rr * 16 + ch * 8 + 2];
                float v3 = myscr[rr * 16 + ch * 8 + 3];
                float v4 = myscr[rr * 16 + ch * 8 + 4];
                float v5 = myscr[rr * 16 + ch * 8 + 5];
                float v6 = myscr[rr * 16 + ch * 8 + 6];
                float v7 = myscr[rr * 16 + ch * 8 + 7];
                if (ok) {
                    h8 hz;
                    hz.a = __floats2half2_rn(v0, v1);
                    hz.b = __floats2half2_rn(v2, v3);
                    hz.c = __floats2half2_rn(v4, v5);
                    hz.d = __floats2half2_rn(v6, v7);
                    *(h8*)(&g_Z1h[rel][(long)gr2 * 64 + nw * 32 + nt * 8 + ch * 4]) = hz;
                }
                int gc0 = rel * 128 + nw * 64 + nt * 16 + ch * 8;
                float pe = v0 * alS[gc0 + 0] + v1 * alS[gc0 + 1]
                         + v2 * alS[gc0 + 2] + v3 * alS[gc0 + 3]
                         + v4 * alS[gc0 + 4] + v5 * alS[gc0 + 5]
                         + v6 * alS[gc0 + 6] + v7 * alS[gc0 + 7];
                float pr = v0 * arS[gc0 + 0] + v1 * arS[gc0 + 1]
                         + v2 * arS[gc0 + 2] + v3 * arS[gc0 + 3]
                         + v4 * arS[gc0 + 4] + v5 * arS[gc0 + 5]
                         + v6 * arS[gc0 + 6] + v7 * arS[gc0 + 7];
                if (nt < 2) { peA += pe; prA += pr; }
                else        { peB += pe; prB += pr; }
                __syncwarp();
            }
            peA += __shfl_xor_sync(0xffffffffu, peA, 1);
            prA += __shfl_xor_sync(0xffffffffu, prA, 1);
            peB += __shfl_xor_sync(0xffffffffu, peB, 1);
            prB += __shfl_xor_sync(0xffffffffu, prB, 1);
            if (ok && ch == 0) {
                int hA = 2 * nw;
                g_EL1[rel][gr2 * 4 + hA] = peA;
                g_ER1[rel][gr2 * 4 + hA] = prA;
                g_EL1[rel][gr2 * 4 + hA + 1] = peB;
                g_ER1[rel][gr2 * 4 + hA + 1] = prB;
            }
        }
        __syncthreads();   // protect Bs refill next relation
    }
}

// ------- layer1 fused CSR aggregation: hoisted metadata, 8-way, fp16 out -----
__global__ __launch_bounds__(256) void k_agg1csr(const float* __restrict__ b1) {
    int w = (blockIdx.x * 256 + threadIdx.x) >> 5;
    if (w >= NN) return;
    int d = w;
    int lane = threadIdx.x & 31, h = lane >> 3;
    float acc0 = 0.f, acc1 = 0.f, acc2 = 0.f, acc3 = 0.f;

    int baseA[RR];
    int cntA[RR];
    float erv[RR];
#pragma unroll
    for (int rel = 0; rel < RR; rel++) {
        int idx = rel * NN + d;
        baseA[rel] = g_off[idx];
        cntA[rel] = g_cnt[idx];
        erv[rel] = g_ER1[rel][d * 4 + h];
    }

#pragma unroll
    for (int rel = 0; rel < RR; rel++) {
        float er = erv[rel];
        int base = baseA[rel], n = cntA[rel];
        float a0 = 0.f, a1 = 0.f, a2 = 0.f, a3 = 0.f, den = 0.f;
        int i = 0;
        for (; i + 8 <= n; i += 8) {
            int s0 = g_csrc[base + i];
            int s1 = g_csrc[base + i + 1];
            int s2 = g_csrc[base + i + 2];
            int s3 = g_csrc[base + i + 3];
            int s4 = g_csrc[base + i + 4];
            int s5 = g_csrc[base + i + 5];
            int s6 = g_csrc[base + i + 6];
            int s7 = g_csrc[base + i + 7];
            float el0 = g_EL1[rel][s0 * 4 + h];
            float el1 = g_EL1[rel][s1 * 4 + h];
            float el2 = g_EL1[rel][s2 * 4 + h];
            float el3 = g_EL1[rel][s3 * 4 + h];
            float el4 = g_EL1[rel][s4 * 4 + h];
            float el5 = g_EL1[rel][s5 * 4 + h];
            float el6 = g_EL1[rel][s6 * 4 + h];
            float el7 = g_EL1[rel][s7 * 4 + h];
            h4 z0 = *(const h4*)&g_Z1h[rel][(long)s0 * 64 + lane * 2];
            h4 z1 = *(const h4*)&g_Z1h[rel][(long)s1 * 64 + lane * 2];
            h4 z2 = *(const h4*)&g_Z1h[rel][(long)s2 * 64 + lane * 2];
            h4 z3 = *(const h4*)&g_Z1h[rel][(long)s3 * 64 + lane * 2];
            h4 z4 = *(const h4*)&g_Z1h[rel][(long)s4 * 64 + lane * 2];
            h4 z5 = *(const h4*)&g_Z1h[rel][(long)s5 * 64 + lane * 2];
            h4 z6 = *(const h4*)&g_Z1h[rel][(long)s6 * 64 + lane * 2];
            h4 z7 = *(const h4*)&g_Z1h[rel][(long)s7 * 64 + lane * 2];
            float p0 = lrexp(el0, er);
            float p1 = lrexp(el1, er);
            float p2 = lrexp(el2, er);
            float p3 = lrexp(el3, er);
            float p4 = lrexp(el4, er);
            float p5 = lrexp(el5, er);
            float p6 = lrexp(el6, er);
            float p7 = lrexp(el7, er);
            float2 q0 = __half22float2(z0.a), r0 = __half22float2(z0.b);
            float2 q1 = __half22float2(z1.a), r1 = __half22float2(z1.b);
            float2 q2 = __half22float2(z2.a), r2 = __half22float2(z2.b);
            float2 q3 = __half22float2(z3.a), r3 = __half22float2(z3.b);
            float2 q4 = __half22float2(z4.a), r4 = __half22float2(z4.b);
            float2 q5 = __half22float2(z5.a), r5 = __half22float2(z5.b);
            float2 q6 = __half22float2(z6.a), r6 = __half22float2(z6.b);
            float2 q7 = __half22float2(z7.a), r7 = __half22float2(z7.b);
            a0 += p0 * q0.x + p1 * q1.x + p2 * q2.x + p3 * q3.x
                + p4 * q4.x + p5 * q5.x + p6 * q6.x + p7 * q7.x;
            a1 += p0 * q0.y + p1 * q1.y + p2 * q2.y + p3 * q3.y
                + p4 * q4.y + p5 * q5.y + p6 * q6.y + p7 * q7.y;
            a2 += p0 * r0.x + p1 * r1.x + p2 * r2.x + p3 * r3.x
                + p4 * r4.x + p5 * r5.x + p6 * r6.x + p7 * r7.x;
            a3 += p0 * r0.y + p1 * r1.y + p2 * r2.y + p3 * r3.y
                + p4 * r4.y + p5 * r5.y + p6 * r6.y + p7 * r7.y;
            den += p0 + p1 + p2 + p3 + p4 + p5 + p6 + p7;
        }
        for (; i < n; i++) {
            int s = g_csrc[base + i];
            float p = lrexp(g_EL1[rel][s * 4 + h], er);
            h4 z = *(const h4*)&g_Z1h[rel][(long)s * 64 + lane * 2];
            float2 zlo = __half22float2(z.a), zhi = __half22float2(z.b);
            a0 += p * zlo.x; a1 += p * zlo.y; a2 += p * zhi.x; a3 += p * zhi.y;
            den += p;
        }
        float rden = (n > 0) ? __frcp_rn(den) : 0.f;
        acc0 += a0 * rden; acc1 += a1 * rden; acc2 += a2 * rden; acc3 += a3 * rden;
    }
    int c = lane * 4;
    float4 bA = *(const float4*)(b1 + c);
    float4 bB = *(const float4*)(b1 + 128 + c);
    float4 bC = *(const float4*)(b1 + 256 + c);
    float v0 = (acc0 + bA.x + bB.x + bC.x) * (1.f / 3.f);
    float v1 = (acc1 + bA.y + bB.y + bC.y) * (1.f / 3.f);
    float v2 = (acc2 + bA.z + bB.z + bC.z) * (1.f / 3.f);
    float v3 = (acc3 + bA.w + bB.w + bC.w) * (1.f / 3.f);
    v0 = v0 > 0.f ? v0 : expm1f(v0);
    v1 = v1 > 0.f ? v1 : expm1f(v1);
    v2 = v2 > 0.f ? v2 : expm1f(v2);
    v3 = v3 > 0.f ? v3 : expm1f(v3);
    h4 hv;
    hv.a = __floats2half2_rn(v0, v1);
    hv.b = __floats2half2_rn(v2, v3);
    *(h4*)(&g_H1h[(long)d * 64 + lane * 2]) = hv;
}

// ---------------- layer2 GEMM via wmma (fp16 H1h input) ----------------------
#define A2STR 136
#define B2STR 24
__global__ __launch_bounds__(256) void k_gemm2_wmma(const float* __restrict__ W2,
                                                    const float* __restrict__ al2,
                                                    const float* __restrict__ ar2) {
    __shared__ __align__(16) char smraw2[40960];
    __shared__ float al2S[16];
    __shared__ float ar2S[16];
    __half* As2 = (__half*)smraw2;
    __half* Bs2 = (__half*)(smraw2 + 34816);
    int rel = blockIdx.z;
    int row0 = blockIdx.x * 128;
    int tid = threadIdx.x;
    int lane = tid & 31;
    int warp = tid >> 5;

    if (tid < 16) {
        al2S[tid] = al2[rel * 16 + tid];
        ar2S[tid] = ar2[rel * 16 + tid];
    }

#pragma unroll
    for (int i = 0; i < 8; i++) {
        int lin = tid + i * 256;
        int r = lin >> 4;
        int ch = lin & 15;
        int gr = row0 + r;
        if (gr >= NN) gr = NN - 1;
        float4 v = *(const float4*)(&g_H1h[(long)gr * 64 + ch * 4]);
        *(float4*)(As2 + r * A2STR + ch * 8) = v;
    }
#pragma unroll
    for (int i = 0; i < 8; i++) {
        int idx = tid + i * 256;
        int r = idx >> 4;
        int c = idx & 15;
        float v = W2[(long)rel * 2048 + r * 16 + c];
        Bs2[r * B2STR + c] = __float2half_rn(v);
    }
    __syncthreads();

    wmma::fragment<wmma::accumulator, 16, 16, 16, float> acc;
    wmma::fill_fragment(acc, 0.f);
#pragma unroll
    for (int ks = 0; ks < 8; ks++) {
        int k0 = ks * 16;
        wmma::fragment<wmma::matrix_a, 16, 16, 16, __half, wmma::row_major> af;
        wmma::fragment<wmma::matrix_b, 16, 16, 16, __half, wmma::row_major> bf;
        wmma::load_matrix_sync(af, As2 + (warp * 16) * A2STR + k0, A2STR);
        wmma::load_matrix_sync(bf, Bs2 + k0 * B2STR, B2STR);
        wmma::mma_sync(acc, af, bf, acc);
    }
    __syncthreads();

    float* scr = (float*)smraw2 + warp * 256;
    wmma::store_matrix_sync(scr, acc, 16, wmma::mem_row_major);
    __syncwarp();

#pragma unroll
    for (int q = 0; q < 8; q++) {
        int idx = lane + q * 32;
        int rr = idx >> 4;
        int cc = idx & 15;
        int row = row0 + warp * 16 + rr;
        if (row < NN) g_Z2[rel][(long)row * 16 + cc] = scr[rr * 16 + cc];
    }
    if (lane < 16) {
        int row = row0 + warp * 16 + lane;
        if (row < NN) {
            float el = 0.f;
            float er = 0.f;
#pragma unroll
            for (int j = 0; j < 16; j++) {
                float zv = scr[lane * 16 + j];
                el += zv * al2S[j];
                er += zv * ar2S[j];
            }
            g_EL2[rel][row] = el;
            g_ER2[rel][row] = er;
        }
    }
}

// ---------------- layer2 fused CSR aggregation (4 per half-warp) -------------
__global__ __launch_bounds__(256) void k_agg2csr(const float* __restrict__ b2,
                                                 float* __restrict__ out) {
    int w = (blockIdx.x * 256 + threadIdx.x) >> 5;
    if (w >= NN) return;
    int d = w;
    int lane = threadIdx.x & 31, hh = lane >> 4, c = lane & 15;
    float acc = 0.f;

#pragma unroll
    for (int rel = 0; rel < RR; rel++) {
        float er = g_ER2[rel][d];
        int idx = rel * NN + d;
        int base = g_off[idx], n = g_cnt[idx];
        float aR = 0.f, den = 0.f;
        int i = hh;
        for (; i + 6 < n; i += 8) {
            int s0 = g_csrc[base + i];
            int s1 = g_csrc[base + i + 2];
            int s2 = g_csrc[base + i + 4];
            int s3 = g_csrc[base + i + 6];
            float e0 = g_EL2[rel][s0];
            float e1 = g_EL2[rel][s1];
            float e2 = g_EL2[rel][s2];
            float e3 = g_EL2[rel][s3];
            float za = g_Z2[rel][s0 * 16 + c];
            float zb = g_Z2[rel][s1 * 16 + c];
            float zc = g_Z2[rel][s2 * 16 + c];
            float zd = g_Z2[rel][s3 * 16 + c];
            float p0 = lrexp(e0, er);
            float p1 = lrexp(e1, er);
            float p2 = lrexp(e2, er);
            float p3 = lrexp(e3, er);
            aR += p0 * za + p1 * zb + p2 * zc + p3 * zd;
            den += p0 + p1 + p2 + p3;
        }
        for (; i < n; i += 2) {
            int s = g_csrc[base + i];
            float p = lrexp(g_EL2[rel][s], er);
            aR += p * g_Z2[rel][s * 16 + c];
            den += p;
        }
        den += __shfl_xor_sync(0xffffffffu, den, 16);
        float rden = (n > 0) ? __frcp_rn(den) : 0.f;
        acc += aR * rden;
    }
    acc += __shfl_xor_sync(0xffffffffu, acc, 16);
    if (hh == 0) {
        float bs = b2[c] + b2[16 + c] + b2[32 + c];
        out[d * 16 + c] = (acc + bs) * (1.f / 3.f);
    }
}

// ---------------- launcher ----------------
extern "C" void kernel_launch(void* const* d_in, const int* in_sizes, int n_in,
                              void* d_out, int out_size) {
    const float* x   = (const float*)d_in[0];
    const int*   src = (const int*)d_in[1];
    const int*   dst = (const int*)d_in[2];
    const float* W1  = (const float*)d_in[3];
    const float* al1 = (const float*)d_in[4];
    const float* ar1 = (const float*)d_in[5];
    const float* b1  = (const float*)d_in[6];
    const float* W2  = (const float*)d_in[7];
    const float* al2 = (const float*)d_in[8];
    const float* ar2 = (const float*)d_in[9];
    const float* b2  = (const float*)d_in[10];
    float* out = (float*)d_out;

    cudaFuncSetAttribute(k_gemm1f, cudaFuncAttributeMaxDynamicSharedMemorySize,
                         77824);

    k_zero_cnt<<<(TOT + 255) / 256, 256>>>();
    dim3 ge((EE + 255) / 256, RR);
    k_hist<<<ge, 256>>>(dst);
    k_scanF<<<SCAN_GRID, 256>>>();

    k_gemm1f<<<(NN + 127) / 128, 256, 77824>>>(x, W1, al1, ar1);  // idx 3 (profiled)

    k_scatter<<<ge, 256>>>(src, dst);

    k_agg1csr<<<(NN * 32 + 255) / 256, 256>>>(b1);

    dim3 gm((NN + 127) / 128, 1, RR);
    k_gemm2_wmma<<<gm, 256>>>(W2, al2, ar2);
    k_agg2csr<<<(NN * 32 + 255) / 256, 256>>>(b2, out);
}